// round 4
// baseline (speedup 1.0000x reference)
#include <cuda_runtime.h>
#include <cuda_fp16.h>
#include <cstdint>
#include <math.h>

#define B_   16
#define C_   192
#define H_   128
#define W_   128
#define NF_  192
#define O4_  768
#define KALL 768
#define KC   64
#define NCHUNK 12      // 768 / 64
#define NTHREADS 256
#define HW_  (H_ * W_)
#define GRIDN 96       // 6 x 16 persistent CTAs

#if defined(__CUDA_ARCH_FEAT_SM103_ALL) || defined(__CUDA_ARCH_FEAT_SM100_ALL) || defined(__CUDA_ARCH_FEAT_SM101_ALL)
#define TC05 1
#else
#define TC05 0
#endif

// ---- persistent device scratch ----
// g_Wt: pre-swizzled fp16 hi/lo weight tiles [mt][cc][hi 16KB | lo 16KB], tile = 128m x 64k
__device__ __half g_Wt[6 * NCHUNK * 2 * 8192];
// g_xt: pre-swizzled fp16 hi/lo x tiles [b][t][cc<3][hi|lo], tile = 128w x 64k
__device__ __half g_xt[(size_t)B_ * H_ * 3 * 2 * 8192];
// g_Wf: full fp32 permuted weights [row][k] (fallback path only)
__device__ float g_Wf[O4_ * KALL];
__device__ float g_h[2][B_ * NF_ * W_];
// grid barrier
__device__ volatile unsigned g_cnt = 0;
__device__ volatile unsigned g_gen = 0;

// ------------------- helpers -------------------
static __device__ __forceinline__ uint32_t smem_u32(const void* p) {
    uint32_t a;
    asm("{ .reg .u64 t; cvta.to.shared.u64 t, %1; cvt.u32.u64 %0, t; }" : "=r"(a) : "l"(p));
    return a;
}
static __device__ __forceinline__ uint32_t pack_h2(__half a, __half b) {
    return (uint32_t)__half_as_ushort(a) | ((uint32_t)__half_as_ushort(b) << 16);
}
static __device__ __forceinline__ float fast_tanh(float x) {
    // 1 - 2/(e^{2x}+1); __expf err ~2ulp; saturates correctly at +/-inf
    return 1.0f - 2.0f / (__expf(2.0f * x) + 1.0f);
}
#define SW128(o) ((uint32_t)(o) ^ ((((uint32_t)(o)) >> 3) & 0x70u))

static __device__ __forceinline__ void grid_sync() {
    __syncthreads();
    if (threadIdx.x == 0) {
        __threadfence();
        unsigned gen = g_gen;
        if (atomicAdd((unsigned*)&g_cnt, 1u) == GRIDN - 1u) {
            g_cnt = 0;
            __threadfence();
            g_gen = gen + 1u;
        } else {
            while (g_gen == gen) { __nanosleep(64); }
            __threadfence();
        }
    }
    __syncthreads();
}

// ------------------- prep kernels -------------------
__global__ void prep_weights(const float* __restrict__ Wf, const float* __restrict__ Uf) {
    int idx = blockIdx.x * blockDim.x + threadIdx.x;
    if (idx >= 6 * 128 * KALL) return;
    int mt = idx / (128 * KALL);
    int m  = (idx / KALL) % 128;
    int k  = idx % KALL;
    int row = mt * 128 + m;
    int co = row >> 2, g = row & 3;
    int o = g * NF_ + co;
    float v;
    if (k < C_) {
        v = Wf[o * C_ + k];
        if ((o < 64 && k >= 64) || (o >= 64 && o < 128 && k >= 128)) v = 0.0f;
    } else {
        int kk = k - C_;
        int c = kk / 3, tau = kk - 3 * c;
        v = Uf[(o * NF_ + c) * 3 + tau];
    }
    g_Wf[row * KALL + k] = v;
    __half vh = __float2half_rn(v);
    __half vl = __float2half_rn(v - __half2float(vh));
    int cc = k >> 6, kl = k & 63;
    size_t tile_base = (size_t)(mt * NCHUNK + cc) * 16384;  // halves (hi 8192 + lo 8192)
    uint32_t swoff = SW128((uint32_t)(m * 128 + kl * 2));   // byte offset in 16KB tile
    char* hp = (char*)(g_Wt + tile_base) + swoff;
    char* lp = (char*)(g_Wt + tile_base + 8192) + swoff;
    *(__half*)hp = vh;
    *(__half*)lp = vl;
}

// one task per (tile, oct, w): tile = (b*128+t)*3+cc; gathers 8 channels at fixed w
__global__ void prep_x(const float* __restrict__ x) {
    int id = blockIdx.x * blockDim.x + threadIdx.x;
    if (id >= B_ * H_ * 3 * 1024) return;
    int tile = id >> 10;
    int inner = id & 1023;
    int oct = inner >> 7;
    int w = inner & 127;
    int cc = tile % 3;
    int t = (tile / 3) % H_;
    int b = tile / (3 * H_);
    __half hh[8], hl[8];
    #pragma unroll
    for (int j = 0; j < 8; ++j) {
        int c = cc * 64 + oct * 8 + j;
        float v = x[((size_t)(b * C_ + c) * H_ + t) * W_ + w];
        hh[j] = __float2half_rn(v);
        hl[j] = __float2half_rn(v - __half2float(hh[j]));
    }
    size_t tb = (size_t)tile * 16384;
    uint32_t swoff = SW128((uint32_t)(w * 128 + oct * 16));
    uint4 uh = make_uint4(pack_h2(hh[0], hh[1]), pack_h2(hh[2], hh[3]),
                          pack_h2(hh[4], hh[5]), pack_h2(hh[6], hh[7]));
    uint4 ul = make_uint4(pack_h2(hl[0], hl[1]), pack_h2(hl[2], hl[3]),
                          pack_h2(hl[4], hl[5]), pack_h2(hl[6], hl[7]));
    *(uint4*)((char*)(g_xt + tb) + swoff) = uh;
    *(uint4*)((char*)(g_xt + tb + 8192) + swoff) = ul;
}

// ------------------- TC05 machinery -------------------
#if TC05
static __device__ __forceinline__ uint32_t elect_one() {
    uint32_t p;
    asm volatile("{ .reg .pred p; elect.sync _|p, 0xFFFFFFFF; selp.b32 %0, 1, 0, p; }" : "=r"(p));
    return p;
}
static __device__ __forceinline__ void mbar_wait(uint32_t mbar, uint32_t parity) {
    asm volatile(
        "{\n\t.reg .pred P;\n\t"
        "WL_%=:\n\t"
        "mbarrier.try_wait.parity.acquire.cta.shared::cta.b64 P, [%0], %1, 0x989680;\n\t"
        "@P bra.uni WD_%=;\n\t"
        "bra.uni WL_%=;\n\t"
        "WD_%=:\n\t}"
        :: "r"(mbar), "r"(parity) : "memory");
}
static __device__ __forceinline__ void mma_f16_ss(uint32_t d, uint64_t da, uint64_t db,
                                                  uint32_t idesc, uint32_t en) {
    asm volatile(
        "{\n\t.reg .pred p;\n\t"
        "setp.ne.u32 p, %4, 0;\n\t"
        "tcgen05.mma.cta_group::1.kind::f16 [%0], %1, %2, %3, {%5, %5, %5, %5}, p;\n\t"
        "}"
        :: "r"(d), "l"(da), "l"(db), "r"(idesc), "r"(en), "r"(0u) : "memory");
}
static __device__ __forceinline__ void tc_commit(uint32_t mbar) {
    asm volatile("tcgen05.commit.cta_group::1.mbarrier::arrive::one.shared::cluster.b64 [%0];"
                 :: "r"(mbar) : "memory");
}
static __device__ __forceinline__ void bulk_cp(uint32_t dst, const void* src, uint32_t bytes,
                                               uint32_t mbar) {
    asm volatile(
        "cp.async.bulk.shared::cluster.global.mbarrier::complete_tx::bytes [%0], [%1], %2, [%3];"
        :: "r"(dst), "l"(src), "r"(bytes), "r"(mbar) : "memory");
}
#define LDTM_X32(r, addr) \
    asm volatile( \
        "tcgen05.ld.sync.aligned.32x32b.x32.b32 " \
        "{%0, %1, %2, %3, %4, %5, %6, %7, " \
        " %8, %9, %10, %11, %12, %13, %14, %15, " \
        " %16, %17, %18, %19, %20, %21, %22, %23, " \
        " %24, %25, %26, %27, %28, %29, %30, %31}, [%32];" \
        : "=r"((r)[0]),  "=r"((r)[1]),  "=r"((r)[2]),  "=r"((r)[3]), \
          "=r"((r)[4]),  "=r"((r)[5]),  "=r"((r)[6]),  "=r"((r)[7]), \
          "=r"((r)[8]),  "=r"((r)[9]),  "=r"((r)[10]), "=r"((r)[11]), \
          "=r"((r)[12]), "=r"((r)[13]), "=r"((r)[14]), "=r"((r)[15]), \
          "=r"((r)[16]), "=r"((r)[17]), "=r"((r)[18]), "=r"((r)[19]), \
          "=r"((r)[20]), "=r"((r)[21]), "=r"((r)[22]), "=r"((r)[23]), \
          "=r"((r)[24]), "=r"((r)[25]), "=r"((r)[26]), "=r"((r)[27]), \
          "=r"((r)[28]), "=r"((r)[29]), "=r"((r)[30]), "=r"((r)[31]) \
        : "r"(addr))

static constexpr uint64_t DESC_BASE_SW128 =
    (uint64_t(2) << 61) | (uint64_t(1) << 46) | (uint64_t(64) << 32) | (uint64_t(1) << 16);
#define MKDESC(a) (DESC_BASE_SW128 | ((uint64_t)(((uint32_t)(a)) >> 4) & 0x3FFFull))
#define IDESC_F16 ((1u << 4) | (16u << 17) | (8u << 24))  // D=F32, A/B=F16, N=128, M=128
#endif

// smem: buf = [AH 16K | AL 16K | BH 16K | BL 16K] x2; epilogue reuses [0, 66KB)
#define T_AH 0
#define T_AL 16384
#define T_BH 32768
#define T_BL 49152
#define BUF_SZ 65536
#define DSMEM  (1024 + 2 * BUF_SZ)
#define EPIP 129   // epilogue pitch (floats): conflict-free both directions

// ------------------- persistent kernel -------------------
__global__ void __launch_bounds__(NTHREADS, 1)
lstm_persist(const float* __restrict__ bias, const float* __restrict__ ih,
             const float* __restrict__ ic, float* __restrict__ out)
{
    extern __shared__ __align__(16) char dsm[];
    const int tid = threadIdx.x;
    const int wid = tid >> 5;
    const int lane = tid & 31;
    const int mt = blockIdx.x;   // 0..5
    const int b  = blockIdx.y;   // 0..15

    const uint32_t raw = smem_u32(dsm);
    const uint32_t dbase = (raw + 1023u) & ~1023u;
    char* dptr = dsm + (dbase - raw);

    // per-thread ownership: co_l = 4*(tid>>5)+i (i<4), w = (tid&31)+32j (j<4)
    const int col0 = 4 * (tid >> 5);
    const int w0 = tid & 31;

    float creg[16];   // [i][j]
    float breg[16];   // [i][g]
    #pragma unroll
    for (int i = 0; i < 4; ++i) {
        int co = mt * 32 + col0 + i;
        #pragma unroll
        for (int g = 0; g < 4; ++g) breg[i * 4 + g] = bias[g * NF_ + co];
        #pragma unroll
        for (int j = 0; j < 4; ++j) {
            int w = w0 + 32 * j;
            creg[i * 4 + j] = ic[co * W_ + w];
            g_h[0][(b * NF_ + co) * W_ + w] = ih[co * W_ + w];
        }
    }

#if TC05
    __shared__ uint32_t s_tmem;
    __shared__ __align__(8) uint64_t s_mbar[4];   // abar0, abar1, mm0, mm1
    if (wid == 0) {
        asm volatile("tcgen05.alloc.cta_group::1.sync.aligned.shared::cta.b32 [%0], %1;"
                     :: "r"(smem_u32(&s_tmem)), "r"(128u) : "memory");
    }
    if (tid == 0) {
        #pragma unroll
        for (int i = 0; i < 4; ++i)
            asm volatile("mbarrier.init.shared.b64 [%0], 1;"
                         :: "r"(smem_u32(&s_mbar[i])) : "memory");
    }
    __syncthreads();
    const uint32_t tmem = s_tmem;
    const uint32_t ab[2] = {smem_u32(&s_mbar[0]), smem_u32(&s_mbar[1])};
    const uint32_t mm[2] = {smem_u32(&s_mbar[2]), smem_u32(&s_mbar[3])};
    float* epi = reinterpret_cast<float*>(dptr);

    grid_sync();   // h init visible

    for (int t = 0; t < H_; ++t) {
        const float* __restrict__ hcur = g_h[t & 1] + b * NF_ * W_;

        for (int cc = 0; cc < NCHUNK; ++cc) {
            const int gc = t * NCHUNK + cc;
            const int buf = cc & 1;
            char* tb = dptr + buf * BUF_SZ;
            const uint32_t sbuf = dbase + buf * BUF_SZ;

            if (gc >= 2) mbar_wait(mm[buf], ((gc >> 1) - 1) & 1);

            if (tid == 0) {
                const char* wsrc = (const char*)g_Wt + (size_t)(mt * NCHUNK + cc) * 32768;
                if (cc < 3) {
                    asm volatile("mbarrier.arrive.expect_tx.shared.b64 _, [%0], %1;"
                                 :: "r"(ab[buf]), "r"(65536u) : "memory");
                    bulk_cp(sbuf + T_AH, wsrc, 32768u, ab[buf]);
                    const char* xsrc = (const char*)g_xt +
                        (size_t)((b * H_ + t) * 3 + cc) * 32768;
                    bulk_cp(sbuf + T_BH, xsrc, 32768u, ab[buf]);
                } else {
                    asm volatile("mbarrier.arrive.expect_tx.shared.b64 _, [%0], %1;"
                                 :: "r"(ab[buf]), "r"(32768u) : "memory");
                    bulk_cp(sbuf + T_AH, wsrc, 32768u, ab[buf]);
                }
            }

            if (cc >= 3) {
                // manual h-im2col fill (fp16 hi/lo split)
                #pragma unroll
                for (int it = 0; it < 4; ++it) {
                    int gid = tid + it * NTHREADS;
                    int oct = gid >> 7, w = gid & 127;
                    __half hh[8], hl[8];
                    #pragma unroll
                    for (int j = 0; j < 8; ++j) {
                        int kk = cc * 64 + oct * 8 + j - C_;
                        int c = kk / 3, tau = kk - 3 * c;
                        int ws = w + tau - 1;
                        float v = ((unsigned)ws < (unsigned)W_)
                                      ? __ldcg(hcur + c * W_ + ws) : 0.0f;
                        hh[j] = __float2half_rn(v);
                        hl[j] = __float2half_rn(v - __half2float(hh[j]));
                    }
                    uint32_t swoff = SW128((uint32_t)(w * 128 + oct * 16));
                    *(uint4*)(tb + T_BH + swoff) =
                        make_uint4(pack_h2(hh[0], hh[1]), pack_h2(hh[2], hh[3]),
                                   pack_h2(hh[4], hh[5]), pack_h2(hh[6], hh[7]));
                    *(uint4*)(tb + T_BL + swoff) =
                        make_uint4(pack_h2(hl[0], hl[1]), pack_h2(hl[2], hl[3]),
                                   pack_h2(hl[4], hl[5]), pack_h2(hl[6], hl[7]));
                }
            }
            __syncthreads();

            if (wid == 0) {
                mbar_wait(ab[buf], (gc >> 1) & 1);
                asm volatile("fence.proxy.async.shared::cta;" ::: "memory");
                if (elect_one()) {
                    uint64_t dAh = MKDESC(sbuf + T_AH);
                    uint64_t dAl = MKDESC(sbuf + T_AL);
                    uint64_t dBh = MKDESC(sbuf + T_BH);
                    uint64_t dBl = MKDESC(sbuf + T_BL);
                    uint64_t pa[3] = {dAh, dAh, dAl};
                    uint64_t pb[3] = {dBh, dBl, dBh};
                    #pragma unroll
                    for (int ps = 0; ps < 3; ++ps) {
                        #pragma unroll
                        for (int ks = 0; ks < 4; ++ks) {
                            uint32_t en = (cc == 0 && ps == 0 && ks == 0) ? 0u : 1u;
                            mma_f16_ss(tmem, pa[ps] + ks * 2, pb[ps] + ks * 2, IDESC_F16, en);
                        }
                    }
                    tc_commit(mm[buf]);
                }
            }
        }

        // drain (last uses this step have parity 1 on both buffers)
        mbar_wait(mm[0], 1u);
        mbar_wait(mm[1], 1u);
        asm volatile("tcgen05.fence::after_thread_sync;" ::: "memory");

        // LDTM stage: 8 warps, warp wid covers rows (wid&3)*32, cols (wid>>2)*32 + it*64
        {
            int row = (wid & 3) * 32 + lane;
            #pragma unroll
            for (int it = 0; it < 2; ++it) {
                int colb = (wid >> 2) * 32 + it * 64;
                uint32_t dr[32];
                LDTM_X32(dr, tmem + colb);
                asm volatile("tcgen05.wait::ld.sync.aligned;" ::: "memory");
                #pragma unroll
                for (int c2 = 0; c2 < 32; ++c2)
                    epi[row * EPIP + colb + c2] = __uint_as_float(dr[c2]);
            }
        }
        asm volatile("tcgen05.fence::before_thread_sync;" ::: "memory");
        __syncthreads();

        // pointwise LSTM update (c in registers)
        float* __restrict__ hnxt = g_h[(t & 1) ^ 1];
        #pragma unroll
        for (int i = 0; i < 4; ++i) {
            int co_l = col0 + i;
            int co = mt * 32 + co_l;
            #pragma unroll
            for (int j = 0; j < 4; ++j) {
                int w = w0 + 32 * j;
                float go = epi[(co_l * 4 + 0) * EPIP + w] + breg[i * 4 + 0];
                float gf = epi[(co_l * 4 + 1) * EPIP + w] + breg[i * 4 + 1];
                float gi = epi[(co_l * 4 + 2) * EPIP + w] + breg[i * 4 + 2];
                float gg = epi[(co_l * 4 + 3) * EPIP + w] + breg[i * 4 + 3];
                float ov = __saturatef(fmaf(0.2f, go, 0.5f));
                float fv = __saturatef(fmaf(0.2f, gf, 0.5f));
                float iv = __saturatef(fmaf(0.2f, gi, 0.5f));
                float cn = fv * creg[i * 4 + j] + iv * fast_tanh(gg);
                creg[i * 4 + j] = cn;
                float hn = ov * fast_tanh(cn);
                hnxt[(b * NF_ + co) * W_ + w] = hn;
                out[((size_t)(b * NF_ + co) * H_ + t) * W_ + w] = hn;
            }
        }
        grid_sync();
    }

    if (wid == 0) {
        asm volatile("tcgen05.dealloc.cta_group::1.sync.aligned.b32 %0, %1;"
                     :: "r"(tmem), "r"(128u));
        asm volatile("tcgen05.relinquish_alloc_permit.cta_group::1.sync.aligned;");
    }
#else
    // ---------- fallback (base-arch pass; never selected when sm_103a cubin exists) ----------
    grid_sync();
    for (int t = 0; t < H_; ++t) {
        const float* hcur = g_h[t & 1] + b * NF_ * W_;
        float* hnxt = g_h[(t & 1) ^ 1];
        #pragma unroll 1
        for (int i = 0; i < 4; ++i) {
            int co_l = col0 + i;
            int co = mt * 32 + co_l;
            const float* wr = g_Wf + (size_t)(mt * 128 + co_l * 4) * KALL;
            #pragma unroll 1
            for (int j = 0; j < 4; ++j) {
                int w = w0 + 32 * j;
                float acc0 = breg[i * 4 + 0], acc1 = breg[i * 4 + 1];
                float acc2 = breg[i * 4 + 2], acc3 = breg[i * 4 + 3];
                const float* xb = (const float*)0;  // x handled via g_xt? fallback uses g_Wf + raw gathers
                (void)xb;
                for (int k = 0; k < KALL; ++k) {
                    float a;
                    if (k < C_) {
                        // x was pre-split into g_xt tiles; recover from hi+lo halves
                        int cc = k >> 6, kl = k & 63;
                        size_t tb2 = (size_t)((b * H_ + t) * 3 + cc) * 16384;
                        uint32_t swoff = SW128((uint32_t)(w * 128 + kl * 2));
                        float vh = __half2float(*(__half*)((char*)(g_xt + tb2) + swoff));
                        float vl = __half2float(*(__half*)((char*)(g_xt + tb2 + 8192) + swoff));
                        a = vh + vl;
                    } else {
                        int kk = k - C_;
                        int c = kk / 3, tau = kk - 3 * c;
                        int ws = w + tau - 1;
                        a = ((unsigned)ws < (unsigned)W_) ? __ldcg(hcur + c * W_ + ws) : 0.0f;
                    }
                    acc0 = fmaf(wr[0 * KALL + k], a, acc0);
                    acc1 = fmaf(wr[1 * KALL + k], a, acc1);
                    acc2 = fmaf(wr[2 * KALL + k], a, acc2);
                    acc3 = fmaf(wr[3 * KALL + k], a, acc3);
                }
                float ov = __saturatef(fmaf(0.2f, acc0, 0.5f));
                float fv = __saturatef(fmaf(0.2f, acc1, 0.5f));
                float iv = __saturatef(fmaf(0.2f, acc2, 0.5f));
                float cn = fv * creg[i * 4 + j] + iv * tanhf(acc3);
                creg[i * 4 + j] = cn;
                float hn = ov * tanhf(cn);
                hnxt[(b * NF_ + co) * W_ + w] = hn;
                out[((size_t)(b * NF_ + co) * H_ + t) * W_ + w] = hn;
                wr += 0;
            }
            wr += 4 * KALL - 4 * KALL;  // no-op
        }
        grid_sync();
    }
#endif
}

// ------------------- launch -------------------
extern "C" void kernel_launch(void* const* d_in, const int* in_sizes, int n_in,
                              void* d_out, int out_size) {
    const float* x  = (const float*)d_in[0];
    const float* Wf = (const float*)d_in[1];
    const float* Uf = (const float*)d_in[2];
    const float* bf = (const float*)d_in[3];
    const float* ih = (const float*)d_in[4];
    const float* ic = (const float*)d_in[5];
    float* out = (float*)d_out;

    cudaFuncSetAttribute(lstm_persist, cudaFuncAttributeMaxDynamicSharedMemorySize, DSMEM);

    prep_weights<<<(6 * 128 * KALL + 255) / 256, 256>>>(Wf, Uf);
    prep_x<<<(B_ * H_ * 3 * 1024 + 255) / 256, 256>>>(x);

    dim3 grid(6, 16);
    lstm_persist<<<grid, NTHREADS, DSMEM>>>(bf, ih, ic, out);
}

// round 5
// speedup vs baseline: 1.4630x; 1.4630x over previous
#include <cuda_runtime.h>
#include <cuda_fp16.h>
#include <cstdint>
#include <math.h>

#define B_   16
#define C_   192
#define H_   128
#define W_   128
#define NF_  192
#define O4_  768
#define KALL 768
#define NCHUNK 12      // 3 x-chunks + 9 U-chunks (tau-major)
#define NTHREADS 256
#define HW_  (H_ * W_)
#define GRIDN 96
#define HT_ROWS 130    // guard row 0, payload 1..128, guard 129
#define HT_PITCH 192   // halves per row

#if defined(__CUDA_ARCH_FEAT_SM103_ALL) || defined(__CUDA_ARCH_FEAT_SM100_ALL) || defined(__CUDA_ARCH_FEAT_SM101_ALL)
#define TC05 1
#else
#define TC05 0
#endif

// ---- persistent device scratch ----
// g_Wt: pre-swizzled fp16 hi/lo A tiles [mt][cc] = 16KB hi + 16KB lo (32KB), SW128
__device__ __align__(1024) __half g_Wt[6 * NCHUNK * 16384];
// g_xt: pre-swizzled fp16 hi/lo x B-tiles [b][t][cc<3] (32KB each)
__device__ __align__(1024) __half g_xt[(size_t)B_ * H_ * 3 * 16384];
// g_Wf: full fp32 permuted weights (fallback only)
__device__ float g_Wf[O4_ * KALL];
// h state: fp16 hi/lo, transposed [row=w+1][c], zero guard rows, double buffered
__device__ __align__(1024) __half g_hTh[2][B_ * HT_ROWS * HT_PITCH];
__device__ __align__(1024) __half g_hTl[2][B_ * HT_ROWS * HT_PITCH];
// grid barrier
__device__ volatile unsigned g_cnt = 0;
__device__ volatile unsigned g_gen = 0;

// ------------------- helpers -------------------
static __device__ __forceinline__ uint32_t smem_u32(const void* p) {
    uint32_t a;
    asm("{ .reg .u64 t; cvta.to.shared.u64 t, %1; cvt.u32.u64 %0, t; }" : "=r"(a) : "l"(p));
    return a;
}
static __device__ __forceinline__ uint32_t pack_h2(__half a, __half b) {
    return (uint32_t)__half_as_ushort(a) | ((uint32_t)__half_as_ushort(b) << 16);
}
static __device__ __forceinline__ float fast_tanh(float x) {
    return 1.0f - 2.0f / (__expf(2.0f * x) + 1.0f);
}
#define SW128(o) ((uint32_t)(o) ^ ((((uint32_t)(o)) >> 3) & 0x70u))

static __device__ __forceinline__ void grid_sync() {
    __syncthreads();
    if (threadIdx.x == 0) {
        __threadfence();
        unsigned gen = g_gen;
        if (atomicAdd((unsigned*)&g_cnt, 1u) == GRIDN - 1u) {
            g_cnt = 0;
            __threadfence();
            g_gen = gen + 1u;
        } else {
            while (g_gen == gen) { __nanosleep(32); }
            __threadfence();
        }
    }
    __syncthreads();
}

// ------------------- prep kernels -------------------
// K ordering: k<192 -> x channel c=k. k>=192: chunk cc=k>>6 (3..11), q=cc-3,
// tau=q/3, cb=q%3, c = cb*64 + (k&63); weight = U[o][c][tau].
__global__ void prep_weights(const float* __restrict__ Wf, const float* __restrict__ Uf) {
    int idx = blockIdx.x * blockDim.x + threadIdx.x;
    if (idx >= 6 * 128 * KALL) return;
    int mt = idx / (128 * KALL);
    int m  = (idx / KALL) % 128;
    int k  = idx % KALL;
    int row = mt * 128 + m;
    int co = row >> 2, g = row & 3;
    int o = g * NF_ + co;
    int cc = k >> 6, kl = k & 63;
    float v;
    if (k < C_) {
        v = Wf[o * C_ + k];
        if ((o < 64 && k >= 64) || (o >= 64 && o < 128 && k >= 128)) v = 0.0f;
    } else {
        int q = cc - 3;
        int tau = q / 3;
        int cb = q - 3 * tau;
        int c = cb * 64 + kl;
        v = Uf[(o * NF_ + c) * 3 + tau];
    }
    g_Wf[row * KALL + k] = v;
    __half vh = __float2half_rn(v);
    __half vl = __float2half_rn(v - __half2float(vh));
    size_t tile_base = (size_t)(mt * NCHUNK + cc) * 16384;   // halves
    uint32_t swoff = SW128((uint32_t)(m * 128 + kl * 2));
    *(__half*)((char*)(g_Wt + tile_base) + swoff) = vh;
    *(__half*)((char*)(g_Wt + tile_base + 8192) + swoff) = vl;
}

__global__ void prep_x(const float* __restrict__ x) {
    int id = blockIdx.x * blockDim.x + threadIdx.x;
    if (id >= B_ * H_ * 3 * 1024) return;
    int tile = id >> 10;
    int inner = id & 1023;
    int oct = inner >> 7;
    int w = inner & 127;
    int cc = tile % 3;
    int t = (tile / 3) % H_;
    int b = tile / (3 * H_);
    __half hh[8], hl[8];
    #pragma unroll
    for (int j = 0; j < 8; ++j) {
        int c = cc * 64 + oct * 8 + j;
        float v = x[((size_t)(b * C_ + c) * H_ + t) * W_ + w];
        hh[j] = __float2half_rn(v);
        hl[j] = __float2half_rn(v - __half2float(hh[j]));
    }
    size_t tb = (size_t)tile * 16384;
    uint32_t swoff = SW128((uint32_t)(w * 128 + oct * 16));
    *(uint4*)((char*)(g_xt + tb) + swoff) =
        make_uint4(pack_h2(hh[0], hh[1]), pack_h2(hh[2], hh[3]),
                   pack_h2(hh[4], hh[5]), pack_h2(hh[6], hh[7]));
    *(uint4*)((char*)(g_xt + tb + 8192) + swoff) =
        make_uint4(pack_h2(hl[0], hl[1]), pack_h2(hl[2], hl[3]),
                   pack_h2(hl[4], hl[5]), pack_h2(hl[6], hl[7]));
}

__global__ void init_hT(const float* __restrict__ ih) {
    int idx = blockIdx.x * blockDim.x + threadIdx.x;
    if (idx >= B_ * HT_ROWS * HT_PITCH) return;
    int c = idx % HT_PITCH;
    int row = (idx / HT_PITCH) % HT_ROWS;
    float v = (row >= 1 && row <= 128) ? ih[c * W_ + (row - 1)] : 0.0f;
    __half vh = __float2half_rn(v);
    __half vl = __float2half_rn(v - __half2float(vh));
    g_hTh[0][idx] = vh; g_hTl[0][idx] = vl;
    g_hTh[1][idx] = vh; g_hTl[1][idx] = vl;
}

// ------------------- TC05 machinery -------------------
#if TC05
static __device__ __forceinline__ uint32_t elect_one() {
    uint32_t p;
    asm volatile("{ .reg .pred p; elect.sync _|p, 0xFFFFFFFF; selp.b32 %0, 1, 0, p; }" : "=r"(p));
    return p;
}
static __device__ __forceinline__ void mbar_wait(uint32_t mbar, uint32_t parity) {
    asm volatile(
        "{\n\t.reg .pred P;\n\t"
        "WL_%=:\n\t"
        "mbarrier.try_wait.parity.acquire.cta.shared::cta.b64 P, [%0], %1, 0x989680;\n\t"
        "@P bra.uni WD_%=;\n\t"
        "bra.uni WL_%=;\n\t"
        "WD_%=:\n\t}"
        :: "r"(mbar), "r"(parity) : "memory");
}
static __device__ __forceinline__ void mma_f16_ss(uint32_t d, uint64_t da, uint64_t db,
                                                  uint32_t idesc, uint32_t en) {
    asm volatile(
        "{\n\t.reg .pred p;\n\t"
        "setp.ne.u32 p, %4, 0;\n\t"
        "tcgen05.mma.cta_group::1.kind::f16 [%0], %1, %2, %3, {%5, %5, %5, %5}, p;\n\t"
        "}"
        :: "r"(d), "l"(da), "l"(db), "r"(idesc), "r"(en), "r"(0u) : "memory");
}
static __device__ __forceinline__ void tc_commit(uint32_t mbar) {
    asm volatile("tcgen05.commit.cta_group::1.mbarrier::arrive::one.shared::cluster.b64 [%0];"
                 :: "r"(mbar) : "memory");
}
static __device__ __forceinline__ void bulk_cp(uint32_t dst, const void* src, uint32_t bytes,
                                               uint32_t mbar) {
    asm volatile(
        "cp.async.bulk.shared::cluster.global.mbarrier::complete_tx::bytes [%0], [%1], %2, [%3];"
        :: "r"(dst), "l"(src), "r"(bytes), "r"(mbar) : "memory");
}
#define LDTM_X32(r, addr) \
    asm volatile( \
        "tcgen05.ld.sync.aligned.32x32b.x32.b32 " \
        "{%0, %1, %2, %3, %4, %5, %6, %7, " \
        " %8, %9, %10, %11, %12, %13, %14, %15, " \
        " %16, %17, %18, %19, %20, %21, %22, %23, " \
        " %24, %25, %26, %27, %28, %29, %30, %31}, [%32];" \
        : "=r"((r)[0]),  "=r"((r)[1]),  "=r"((r)[2]),  "=r"((r)[3]), \
          "=r"((r)[4]),  "=r"((r)[5]),  "=r"((r)[6]),  "=r"((r)[7]), \
          "=r"((r)[8]),  "=r"((r)[9]),  "=r"((r)[10]), "=r"((r)[11]), \
          "=r"((r)[12]), "=r"((r)[13]), "=r"((r)[14]), "=r"((r)[15]), \
          "=r"((r)[16]), "=r"((r)[17]), "=r"((r)[18]), "=r"((r)[19]), \
          "=r"((r)[20]), "=r"((r)[21]), "=r"((r)[22]), "=r"((r)[23]), \
          "=r"((r)[24]), "=r"((r)[25]), "=r"((r)[26]), "=r"((r)[27]), \
          "=r"((r)[28]), "=r"((r)[29]), "=r"((r)[30]), "=r"((r)[31]) \
        : "r"(addr))

static constexpr uint64_t DESC_BASE_SW128 =
    (uint64_t(2) << 61) | (uint64_t(1) << 46) | (uint64_t(64) << 32) | (uint64_t(1) << 16);
#define MKDESC(a) (DESC_BASE_SW128 | ((uint64_t)(((uint32_t)(a)) >> 4) & 0x3FFFull))
#define IDESC_F16 ((1u << 4) | (16u << 17) | (8u << 24))  // D=F32, A/B=F16, N=128, M=128
#endif

#define T_AH 0
#define T_AL 16384
#define T_BH 32768
#define T_BL 49152
#define BUF_SZ 65536
#define DSMEM  (1024 + 2 * BUF_SZ)
#define EPIP 129

// ------------------- persistent kernel -------------------
__global__ void __launch_bounds__(NTHREADS, 1)
lstm_persist(const float* __restrict__ bias, const float* __restrict__ ic,
             float* __restrict__ out)
{
    extern __shared__ __align__(16) char dsm[];
    const int tid = threadIdx.x;
    const int wid = tid >> 5;
    const int lane = tid & 31;
    const int mt = blockIdx.x;   // 0..5
    const int b  = blockIdx.y;   // 0..15

    const uint32_t raw = smem_u32(dsm);
    const uint32_t dbase = (raw + 1023u) & ~1023u;
    char* dptr = dsm + (dbase - raw);

    const int col0 = 4 * (tid >> 5);  // 4 consecutive local co
    const int w0 = tid & 31;

    float creg[16];   // [i][j]
    float breg[16];
    #pragma unroll
    for (int i = 0; i < 4; ++i) {
        int co = mt * 32 + col0 + i;
        #pragma unroll
        for (int g = 0; g < 4; ++g) breg[i * 4 + g] = bias[g * NF_ + co];
        #pragma unroll
        for (int j = 0; j < 4; ++j)
            creg[i * 4 + j] = ic[co * W_ + (w0 + 32 * j)];
    }

#if TC05
    __shared__ uint32_t s_tmem;
    __shared__ __align__(8) uint64_t s_mbar[4];   // ab0, ab1, mm0, mm1
    if (wid == 0) {
        asm volatile("tcgen05.alloc.cta_group::1.sync.aligned.shared::cta.b32 [%0], %1;"
                     :: "r"(smem_u32(&s_tmem)), "r"(128u) : "memory");
    }
    if (tid == 0) {
        #pragma unroll
        for (int i = 0; i < 4; ++i)
            asm volatile("mbarrier.init.shared.b64 [%0], 1;"
                         :: "r"(smem_u32(&s_mbar[i])) : "memory");
    }
    __syncthreads();
    const uint32_t tmem = s_tmem;
    const uint32_t ab[2] = {smem_u32(&s_mbar[0]), smem_u32(&s_mbar[1])};
    const uint32_t mm[2] = {smem_u32(&s_mbar[2]), smem_u32(&s_mbar[3])};
    float* epi = reinterpret_cast<float*>(dptr);

    grid_sync();   // init_hT visible

    for (int t = 0; t < H_; ++t) {
        const int p = t & 1;
        const __half* __restrict__ hth = g_hTh[p] + (size_t)b * HT_ROWS * HT_PITCH;
        const __half* __restrict__ htl = g_hTl[p] + (size_t)b * HT_ROWS * HT_PITCH;

        for (int cc = 0; cc < NCHUNK; ++cc) {
            const int gc = t * NCHUNK + cc;
            const int buf = cc & 1;
            char* tb = dptr + buf * BUF_SZ;
            const uint32_t sbuf = dbase + buf * BUF_SZ;

            if (gc >= 2) mbar_wait(mm[buf], ((gc >> 1) - 1) & 1);

            if (tid == 0) {
                const char* wsrc = (const char*)g_Wt + (size_t)(mt * NCHUNK + cc) * 32768;
                if (cc < 3) {
                    asm volatile("mbarrier.arrive.expect_tx.shared.b64 _, [%0], %1;"
                                 :: "r"(ab[buf]), "r"(65536u) : "memory");
                    bulk_cp(sbuf + T_AH, wsrc, 32768u, ab[buf]);
                    const char* xsrc = (const char*)g_xt +
                        (size_t)((b * H_ + t) * 3 + cc) * 32768;
                    bulk_cp(sbuf + T_BH, xsrc, 32768u, ab[buf]);
                } else {
                    asm volatile("mbarrier.arrive.expect_tx.shared.b64 _, [%0], %1;"
                                 :: "r"(ab[buf]), "r"(32768u) : "memory");
                    bulk_cp(sbuf + T_AH, wsrc, 32768u, ab[buf]);
                }
            }

            if (cc >= 3) {
                // pure-copy h fill: B row w <- hT[w+tau][cb*64 .. +64), 128B hi + 128B lo
                const int q = cc - 3;
                const int tau = q / 3;
                const int cb = q - 3 * tau;
                const int plane = tid >> 7;      // 0: hi, 1: lo
                const int row = tid & 127;
                const __half* src = (plane ? htl : hth) +
                                    (size_t)(row + tau) * HT_PITCH + cb * 64;
                char* dst = tb + (plane ? T_BL : T_BH);
                #pragma unroll
                for (int i = 0; i < 8; ++i) {
                    uint4 v = __ldcg(reinterpret_cast<const uint4*>(src) + i);
                    *(uint4*)(dst + SW128((uint32_t)(row * 128 + i * 16))) = v;
                }
            }
            __syncthreads();

            if (wid == 0) {
                mbar_wait(ab[buf], (gc >> 1) & 1);
                asm volatile("fence.proxy.async.shared::cta;" ::: "memory");
                if (elect_one()) {
                    uint64_t dAh = MKDESC(sbuf + T_AH);
                    uint64_t dAl = MKDESC(sbuf + T_AL);
                    uint64_t dBh = MKDESC(sbuf + T_BH);
                    uint64_t dBl = MKDESC(sbuf + T_BL);
                    uint64_t pa[3] = {dAh, dAh, dAl};
                    uint64_t pb[3] = {dBh, dBl, dBh};
                    #pragma unroll
                    for (int ps = 0; ps < 3; ++ps) {
                        #pragma unroll
                        for (int ks = 0; ks < 4; ++ks) {
                            uint32_t en = (cc == 0 && ps == 0 && ks == 0) ? 0u : 1u;
                            mma_f16_ss(tmem, pa[ps] + ks * 2, pb[ps] + ks * 2, IDESC_F16, en);
                        }
                    }
                    tc_commit(mm[buf]);
                }
            }
        }

        // drain
        mbar_wait(mm[0], 1u);
        mbar_wait(mm[1], 1u);
        asm volatile("tcgen05.fence::after_thread_sync;" ::: "memory");

        // LDTM -> smem stage
        {
            int row = (wid & 3) * 32 + lane;
            #pragma unroll
            for (int it = 0; it < 2; ++it) {
                int colb = (wid >> 2) * 32 + it * 64;
                uint32_t dr[32];
                LDTM_X32(dr, tmem + colb);
                asm volatile("tcgen05.wait::ld.sync.aligned;" ::: "memory");
                #pragma unroll
                for (int c2 = 0; c2 < 32; ++c2)
                    epi[row * EPIP + colb + c2] = __uint_as_float(dr[c2]);
            }
        }
        asm volatile("tcgen05.fence::before_thread_sync;" ::: "memory");
        __syncthreads();

        // pointwise LSTM + h emit (fp16 hi/lo, transposed with guard offset)
        __half* hh_out = g_hTh[p ^ 1] + (size_t)b * HT_ROWS * HT_PITCH;
        __half* hl_out = g_hTl[p ^ 1] + (size_t)b * HT_ROWS * HT_PITCH;
        #pragma unroll
        for (int j = 0; j < 4; ++j) {
            int w = w0 + 32 * j;
            float hnv[4];
            #pragma unroll
            for (int i = 0; i < 4; ++i) {
                int co_l = col0 + i;
                int co = mt * 32 + co_l;
                float go = epi[(co_l * 4 + 0) * EPIP + w] + breg[i * 4 + 0];
                float gf = epi[(co_l * 4 + 1) * EPIP + w] + breg[i * 4 + 1];
                float gi = epi[(co_l * 4 + 2) * EPIP + w] + breg[i * 4 + 2];
                float gg = epi[(co_l * 4 + 3) * EPIP + w] + breg[i * 4 + 3];
                float ov = __saturatef(fmaf(0.2f, go, 0.5f));
                float fv = __saturatef(fmaf(0.2f, gf, 0.5f));
                float iv = __saturatef(fmaf(0.2f, gi, 0.5f));
                float cn = fv * creg[i * 4 + j] + iv * fast_tanh(gg);
                creg[i * 4 + j] = cn;
                float hn = ov * fast_tanh(cn);
                hnv[i] = hn;
                out[((size_t)(b * NF_ + co) * H_ + t) * W_ + w] = hn;
            }
            __half h0 = __float2half_rn(hnv[0]), h1 = __float2half_rn(hnv[1]);
            __half h2 = __float2half_rn(hnv[2]), h3 = __float2half_rn(hnv[3]);
            __half l0 = __float2half_rn(hnv[0] - __half2float(h0));
            __half l1 = __float2half_rn(hnv[1] - __half2float(h1));
            __half l2 = __float2half_rn(hnv[2] - __half2float(h2));
            __half l3 = __float2half_rn(hnv[3] - __half2float(h3));
            size_t hb = (size_t)(w + 1) * HT_PITCH + (mt * 32 + col0);
            *(uint2*)(hh_out + hb) = make_uint2(pack_h2(h0, h1), pack_h2(h2, h3));
            *(uint2*)(hl_out + hb) = make_uint2(pack_h2(l0, l1), pack_h2(l2, l3));
        }
        grid_sync();
    }

    if (wid == 0) {
        asm volatile("tcgen05.dealloc.cta_group::1.sync.aligned.b32 %0, %1;"
                     :: "r"(tmem), "r"(128u));
        asm volatile("tcgen05.relinquish_alloc_permit.cta_group::1.sync.aligned;");
    }
#else
    // ---------- fallback (never selected when sm_103a cubin exists) ----------
    grid_sync();
    for (int t = 0; t < H_; ++t) {
        const int p = t & 1;
        const __half* hth = g_hTh[p] + (size_t)b * HT_ROWS * HT_PITCH;
        const __half* htl = g_hTl[p] + (size_t)b * HT_ROWS * HT_PITCH;
        __half* hh_out = g_hTh[p ^ 1] + (size_t)b * HT_ROWS * HT_PITCH;
        __half* hl_out = g_hTl[p ^ 1] + (size_t)b * HT_ROWS * HT_PITCH;
        #pragma unroll 1
        for (int i = 0; i < 4; ++i) {
            int co_l = col0 + i;
            int co = mt * 32 + co_l;
            #pragma unroll 1
            for (int j = 0; j < 4; ++j) {
                int w = w0 + 32 * j;
                float acc[4] = {breg[i*4+0], breg[i*4+1], breg[i*4+2], breg[i*4+3]};
                for (int k = 0; k < KALL; ++k) {
                    int cc = k >> 6, kl = k & 63;
                    float a;
                    if (k < C_) {
                        size_t tb2 = (size_t)((b * H_ + t) * 3 + cc) * 16384;
                        uint32_t swoff = SW128((uint32_t)(w * 128 + kl * 2));
                        a = __half2float(*(__half*)((char*)(g_xt + tb2) + swoff)) +
                            __half2float(*(__half*)((char*)(g_xt + tb2 + 8192) + swoff));
                    } else {
                        int q = cc - 3;
                        int tau = q / 3;
                        int cb = q - 3 * tau;
                        int c = cb * 64 + kl;
                        size_t hi = (size_t)(w + tau) * HT_PITCH + c;
                        a = __half2float(hth[hi]) + __half2float(htl[hi]);
                    }
                    #pragma unroll
                    for (int g = 0; g < 4; ++g)
                        acc[g] = fmaf(g_Wf[(size_t)((mt*32+co_l)*4+g) * KALL + k], a, acc[g]);
                }
                float ov = __saturatef(fmaf(0.2f, acc[0], 0.5f));
                float fv = __saturatef(fmaf(0.2f, acc[1], 0.5f));
                float iv = __saturatef(fmaf(0.2f, acc[2], 0.5f));
                float cn = fv * creg[i*4+j] + iv * tanhf(acc[3]);
                creg[i*4+j] = cn;
                float hn = ov * tanhf(cn);
                out[((size_t)(b * NF_ + co) * H_ + t) * W_ + w] = hn;
                __half vh = __float2half_rn(hn);
                __half vl = __float2half_rn(hn - __half2float(vh));
                size_t hb = (size_t)(w + 1) * HT_PITCH + co;
                hh_out[hb] = vh;
                hl_out[hb] = vl;
            }
        }
        grid_sync();
    }
#endif
}

// ------------------- launch -------------------
extern "C" void kernel_launch(void* const* d_in, const int* in_sizes, int n_in,
                              void* d_out, int out_size) {
    const float* x  = (const float*)d_in[0];
    const float* Wf = (const float*)d_in[1];
    const float* Uf = (const float*)d_in[2];
    const float* bf = (const float*)d_in[3];
    const float* ih = (const float*)d_in[4];
    const float* ic = (const float*)d_in[5];
    float* out = (float*)d_out;

    cudaFuncSetAttribute(lstm_persist, cudaFuncAttributeMaxDynamicSharedMemorySize, DSMEM);

    prep_weights<<<(6 * 128 * KALL + 255) / 256, 256>>>(Wf, Uf);
    prep_x<<<(B_ * H_ * 3 * 1024 + 255) / 256, 256>>>(x);
    init_hT<<<(B_ * HT_ROWS * HT_PITCH + 255) / 256, 256>>>(ih);

    dim3 grid(6, 16);
    lstm_persist<<<grid, NTHREADS, DSMEM>>>(bf, ic, out);
}